// round 9
// baseline (speedup 1.0000x reference)
#include <cuda_runtime.h>
#include <mma.h>
#include <math.h>
#include <stdint.h>

using namespace nvcuda;

#define N_NODES 50000
#define N_EDGES 800000
#define IN_CH   128
#define F1      256   // heads*out layer1
#define F2      64
#define H1      4

#define CHUNK0  25088   // 128*196, multiple of 16
#define CHUNK1  (N_NODES - CHUNK0)   // 24912 = 16*1557

// ---------------- scratch (device globals; no allocation allowed) -----------
__device__ float g_q1[N_NODES * F1];
__device__ float g_k1[N_NODES * F1];
__device__ float g_v1[N_NODES * F1];
__device__ float g_r1[N_NODES * F1];
__device__ float g_h[N_NODES * F1];

__device__ float g_q2[N_NODES * F2];
__device__ float g_k2[N_NODES * F2];
__device__ float g_v2[N_NODES * F2];
__device__ float g_r2[N_NODES * F2];

__device__ float g_btile1[4 * 16 * F1];
__device__ float g_btile2[4 * 16 * F2];

// CSR scratch
#define SCAN_NBLK ((N_NODES + 1023) / 1024)   // 49
__device__ int g_deg[N_NODES];
__device__ int g_off[N_NODES + 1];
__device__ int g_pos[N_NODES];
__device__ int g_csr_src[N_EDGES];
__device__ int g_bsum[SCAN_NBLK];
__device__ int g_bscan[SCAN_NBLK];

// ---------------- cp.async helpers ------------------------------------------
__device__ __forceinline__ void cp_async16(uint32_t saddr, const void* gptr) {
    asm volatile("cp.async.cg.shared.global [%0], [%1], 16;\n"
                 :: "r"(saddr), "l"(gptr));
}
__device__ __forceinline__ void cp_commit() {
    asm volatile("cp.async.commit_group;\n");
}
template <int N>
__device__ __forceinline__ void cp_wait() {
    asm volatile("cp.async.wait_group %0;\n" :: "n"(N));
}

// ---------------- CSR build --------------------------------------------------
__global__ void deg_count_kernel(const int* __restrict__ dst) {
    int e = blockIdx.x * blockDim.x + threadIdx.x;
    if (e < N_EDGES) atomicAdd(&g_deg[dst[e]], 1);
}

__global__ void scan1_kernel() {
    __shared__ int ss[256];
    int t = threadIdx.x;
    int base = blockIdx.x * 1024 + t * 4;
    int d0 = (base     < N_NODES) ? g_deg[base]     : 0;
    int d1 = (base + 1 < N_NODES) ? g_deg[base + 1] : 0;
    int d2 = (base + 2 < N_NODES) ? g_deg[base + 2] : 0;
    int d3 = (base + 3 < N_NODES) ? g_deg[base + 3] : 0;
    int s = d0 + d1 + d2 + d3;
    ss[t] = s;
    __syncthreads();
    for (int off = 1; off < 256; off <<= 1) {
        int v = (t >= off) ? ss[t - off] : 0;
        __syncthreads();
        ss[t] += v;
        __syncthreads();
    }
    int ex = ss[t] - s;
    int e0 = ex, e1 = ex + d0, e2 = e1 + d1, e3 = e2 + d2;
    if (base     < N_NODES) g_off[base]     = e0;
    if (base + 1 < N_NODES) g_off[base + 1] = e1;
    if (base + 2 < N_NODES) g_off[base + 2] = e2;
    if (base + 3 < N_NODES) g_off[base + 3] = e3;
    if (t == 255) g_bsum[blockIdx.x] = ss[255];
}

__global__ void scan2_kernel() {
    __shared__ int ss[64];
    int t = threadIdx.x;
    int v = (t < SCAN_NBLK) ? g_bsum[t] : 0;
    ss[t] = v;
    __syncthreads();
    for (int off = 1; off < 64; off <<= 1) {
        int u = (t >= off) ? ss[t - off] : 0;
        __syncthreads();
        ss[t] += u;
        __syncthreads();
    }
    if (t < SCAN_NBLK) g_bscan[t] = ss[t] - v;
    if (t == SCAN_NBLK - 1) g_off[N_NODES] = ss[t];
}

__global__ void scan3_kernel() {
    int t = threadIdx.x;
    int add = g_bscan[blockIdx.x];
    int base = blockIdx.x * 1024 + t * 4;
#pragma unroll
    for (int i = 0; i < 4; i++) {
        int idx = base + i;
        if (idx < N_NODES) {
            int v = g_off[idx] + add;
            g_off[idx] = v;
            g_pos[idx] = v;
        }
    }
}

__global__ void scatter_kernel(const int* __restrict__ src, const int* __restrict__ dst) {
    int e = blockIdx.x * blockDim.x + threadIdx.x;
    if (e < N_EDGES) {
        int slot = atomicAdd(&g_pos[dst[e]], 1);
        g_csr_src[slot] = src[e];
    }
}

// ---------------- bias tile: 16 identical rows per GEMM ----------------------
__global__ void btile_kernel(const float* __restrict__ b0, const float* __restrict__ b1,
                             const float* __restrict__ b2, const float* __restrict__ b3,
                             float* __restrict__ out, int Nn) {
    int i = blockIdx.x * blockDim.x + threadIdx.x;
    int total = 4 * 16 * Nn;
    if (i >= total) return;
    int z = i / (16 * Nn);
    int c = i % Nn;
    const float* b = (z == 0) ? b0 : (z == 1) ? b1 : (z == 2) ? b2 : b3;
    out[i] = b[c];
}

// ---------------- TF32 GEMM + bias, BK=32, 4 warps, 64x32 warp tile ----------
// C_z = A @ B_z + bias_z. Caller may pass row-offset A/C with M = chunk size
// (must be a multiple of 16).
#define GEMM_SMEM ((2 * 128 * 36 + 2 * 32 * 68) * 4)   // 54272 bytes

__global__ __launch_bounds__(128) void gemm4_tf32(
        const float* __restrict__ A,
        const float* __restrict__ B0, const float* __restrict__ B1,
        const float* __restrict__ B2, const float* __restrict__ B3,
        float* __restrict__ C0, float* __restrict__ C1,
        float* __restrict__ C2, float* __restrict__ C3,
        const float* __restrict__ btile,
        int M, int Nn, int K) {
    const float* B;
    float* C;
    switch (blockIdx.z) {
        case 0: B = B0; C = C0; break;
        case 1: B = B1; C = C1; break;
        case 2: B = B2; C = C2; break;
        default: B = B3; C = C3; break;
    }
    const float* biasT = btile + (size_t)blockIdx.z * 16 * Nn;

    extern __shared__ float dsm[];
    float (*As)[128][36] = reinterpret_cast<float(*)[128][36]>(dsm);
    float (*Bs)[32][68]  = reinterpret_cast<float(*)[32][68]>(dsm + 2 * 128 * 36);

    int tid = threadIdx.x;
    int warp = tid >> 5;
    int wm = warp & 1;
    int wn = warp >> 1;
    int rowBase = blockIdx.y * 128;
    int colBase = blockIdx.x * 64;

    int aRow = tid >> 3;
    int aCol = (tid & 7) * 4;
    int bRow = tid >> 4;
    int bCol = (tid & 15) * 4;

    int grA[8];
#pragma unroll
    for (int r = 0; r < 8; r++) {
        int rr = rowBase + aRow + r * 16;
        grA[r] = rr < M ? rr : M - 1;
    }

    uint32_t aBase[2], bBase[2];
#pragma unroll
    for (int st = 0; st < 2; st++) {
        aBase[st] = (uint32_t)__cvta_generic_to_shared(&As[st][aRow][aCol]);
        bBase[st] = (uint32_t)__cvta_generic_to_shared(&Bs[st][bRow][bCol]);
    }

    wmma::fragment<wmma::accumulator, 16, 16, 8, float> acc[4][2];
#pragma unroll
    for (int i = 0; i < 4; i++)
#pragma unroll
        for (int j = 0; j < 2; j++)
            wmma::load_matrix_sync(acc[i][j], &biasT[colBase + wn * 32 + j * 16],
                                   Nn, wmma::mem_row_major);

#pragma unroll
    for (int r = 0; r < 8; r++)
        cp_async16(aBase[0] + r * (16 * 36 * 4), &A[(size_t)grA[r] * K + aCol]);
#pragma unroll
    for (int r = 0; r < 4; r++)
        cp_async16(bBase[0] + r * (8 * 68 * 4),
                   &B[(size_t)(bRow + r * 8) * Nn + colBase + bCol]);
    cp_commit();

    int st = 0;
    for (int k0 = 0; k0 < K; k0 += 32) {
        if (k0 + 32 < K) {
            int ns = st ^ 1;
#pragma unroll
            for (int r = 0; r < 8; r++)
                cp_async16(aBase[ns] + r * (16 * 36 * 4),
                           &A[(size_t)grA[r] * K + k0 + 32 + aCol]);
#pragma unroll
            for (int r = 0; r < 4; r++)
                cp_async16(bBase[ns] + r * (8 * 68 * 4),
                           &B[(size_t)(k0 + 32 + bRow + r * 8) * Nn + colBase + bCol]);
        }
        cp_commit();
        cp_wait<1>();
        __syncthreads();

#pragma unroll
        for (int ks = 0; ks < 32; ks += 8) {
            wmma::fragment<wmma::matrix_a, 16, 16, 8, wmma::precision::tf32, wmma::row_major> af[4];
            wmma::fragment<wmma::matrix_b, 16, 16, 8, wmma::precision::tf32, wmma::row_major> bf[2];
#pragma unroll
            for (int i = 0; i < 4; i++) {
                wmma::load_matrix_sync(af[i], &As[st][wm * 64 + i * 16][ks], 36);
#pragma unroll
                for (int t = 0; t < af[i].num_elements; t++)
                    af[i].x[t] = wmma::__float_to_tf32(af[i].x[t]);
            }
#pragma unroll
            for (int j = 0; j < 2; j++) {
                wmma::load_matrix_sync(bf[j], &Bs[st][ks][wn * 32 + j * 16], 68);
#pragma unroll
                for (int t = 0; t < bf[j].num_elements; t++)
                    bf[j].x[t] = wmma::__float_to_tf32(bf[j].x[t]);
            }
#pragma unroll
            for (int i = 0; i < 4; i++)
#pragma unroll
                for (int j = 0; j < 2; j++)
                    wmma::mma_sync(acc[i][j], af[i], bf[j], acc[i][j]);
        }
        __syncthreads();
        st ^= 1;
    }

#pragma unroll
    for (int i = 0; i < 4; i++) {
        int r = rowBase + wm * 64 + i * 16;
        if (r < M) {   // M % 16 == 0 -> fragment fully valid
#pragma unroll
            for (int j = 0; j < 2; j++)
                wmma::store_matrix_sync(&C[(size_t)r * Nn + colBase + wn * 32 + j * 16],
                                        acc[i][j], Nn, wmma::mem_row_major);
        }
    }
}

// ---------------- layer1: attention + beta + relu, warp per node, ILP2 ------
// Processes nodes [nBase, nBase + nCount).
__global__ __launch_bounds__(128) void attn1_beta_kernel(
        const float* __restrict__ q, const float* __restrict__ k,
        const float* __restrict__ v, const float* __restrict__ r,
        const float* __restrict__ wb, float* __restrict__ h,
        int nBase, int nCount) {
    int wid = (blockIdx.x * blockDim.x + threadIdx.x) >> 5;
    if (wid >= nCount) return;
    int n = nBase + wid;
    int lane = threadIdx.x & 31;
    int col = lane * 8;

    float4 q0 = *reinterpret_cast<const float4*>(&q[(size_t)n * F1 + col]);
    float4 q1 = *reinterpret_cast<const float4*>(&q[(size_t)n * F1 + col + 4]);

    int beg = g_off[n], end = g_off[n + 1];

    float mA = -3.4e38f, sA = 0.f, mB = -3.4e38f, sB = 0.f;
    float4 aA0 = {0,0,0,0}, aA1 = {0,0,0,0}, aB0 = {0,0,0,0}, aB1 = {0,0,0,0};

    int i = beg;
    for (; i + 2 <= end; i += 2) {
        int s0 = g_csr_src[i], s1 = g_csr_src[i + 1];
        size_t b0 = (size_t)s0 * F1 + col, b1 = (size_t)s1 * F1 + col;
        float4 kA0 = *reinterpret_cast<const float4*>(&k[b0]);
        float4 kA1 = *reinterpret_cast<const float4*>(&k[b0 + 4]);
        float4 kB0 = *reinterpret_cast<const float4*>(&k[b1]);
        float4 kB1 = *reinterpret_cast<const float4*>(&k[b1 + 4]);
        float4 vA0 = *reinterpret_cast<const float4*>(&v[b0]);
        float4 vA1 = *reinterpret_cast<const float4*>(&v[b0 + 4]);
        float4 vB0 = *reinterpret_cast<const float4*>(&v[b1]);
        float4 vB1 = *reinterpret_cast<const float4*>(&v[b1 + 4]);

        float dA = q0.x*kA0.x + q0.y*kA0.y + q0.z*kA0.z + q0.w*kA0.w
                 + q1.x*kA1.x + q1.y*kA1.y + q1.z*kA1.z + q1.w*kA1.w;
        float dB = q0.x*kB0.x + q0.y*kB0.y + q0.z*kB0.z + q0.w*kB0.w
                 + q1.x*kB1.x + q1.y*kB1.y + q1.z*kB1.z + q1.w*kB1.w;
        dA += __shfl_xor_sync(0xFFFFFFFFu, dA, 1);
        dB += __shfl_xor_sync(0xFFFFFFFFu, dB, 1);
        dA += __shfl_xor_sync(0xFFFFFFFFu, dA, 2);
        dB += __shfl_xor_sync(0xFFFFFFFFu, dB, 2);
        dA += __shfl_xor_sync(0xFFFFFFFFu, dA, 4);
        dB += __shfl_xor_sync(0xFFFFFFFFu, dB, 4);
        dA *= 0.125f; dB *= 0.125f;

        float mnA = fmaxf(mA, dA), mnB = fmaxf(mB, dB);
        float cA = __expf(mA - mnA), cB = __expf(mB - mnB);
        float pA = __expf(dA - mnA), pB = __expf(dB - mnB);
        sA = sA * cA + pA; sB = sB * cB + pB;
        aA0.x = aA0.x*cA + pA*vA0.x; aA0.y = aA0.y*cA + pA*vA0.y;
        aA0.z = aA0.z*cA + pA*vA0.z; aA0.w = aA0.w*cA + pA*vA0.w;
        aA1.x = aA1.x*cA + pA*vA1.x; aA1.y = aA1.y*cA + pA*vA1.y;
        aA1.z = aA1.z*cA + pA*vA1.z; aA1.w = aA1.w*cA + pA*vA1.w;
        aB0.x = aB0.x*cB + pB*vB0.x; aB0.y = aB0.y*cB + pB*vB0.y;
        aB0.z = aB0.z*cB + pB*vB0.z; aB0.w = aB0.w*cB + pB*vB0.w;
        aB1.x = aB1.x*cB + pB*vB1.x; aB1.y = aB1.y*cB + pB*vB1.y;
        aB1.z = aB1.z*cB + pB*vB1.z; aB1.w = aB1.w*cB + pB*vB1.w;
        mA = mnA; mB = mnB;
    }
    if (i < end) {
        int s0 = g_csr_src[i];
        size_t b0 = (size_t)s0 * F1 + col;
        float4 kA0 = *reinterpret_cast<const float4*>(&k[b0]);
        float4 kA1 = *reinterpret_cast<const float4*>(&k[b0 + 4]);
        float4 vA0 = *reinterpret_cast<const float4*>(&v[b0]);
        float4 vA1 = *reinterpret_cast<const float4*>(&v[b0 + 4]);
        float dA = q0.x*kA0.x + q0.y*kA0.y + q0.z*kA0.z + q0.w*kA0.w
                 + q1.x*kA1.x + q1.y*kA1.y + q1.z*kA1.z + q1.w*kA1.w;
        dA += __shfl_xor_sync(0xFFFFFFFFu, dA, 1);
        dA += __shfl_xor_sync(0xFFFFFFFFu, dA, 2);
        dA += __shfl_xor_sync(0xFFFFFFFFu, dA, 4);
        dA *= 0.125f;
        float mnA = fmaxf(mA, dA);
        float cA = __expf(mA - mnA), pA = __expf(dA - mnA);
        sA = sA * cA + pA;
        aA0.x = aA0.x*cA + pA*vA0.x; aA0.y = aA0.y*cA + pA*vA0.y;
        aA0.z = aA0.z*cA + pA*vA0.z; aA0.w = aA0.w*cA + pA*vA0.w;
        aA1.x = aA1.x*cA + pA*vA1.x; aA1.y = aA1.y*cA + pA*vA1.y;
        aA1.z = aA1.z*cA + pA*vA1.z; aA1.w = aA1.w*cA + pA*vA1.w;
        mA = mnA;
    }
    float mn = fmaxf(mA, mB);
    float cA = __expf(mA - mn), cB = __expf(mB - mn);
    float ssum = sA * cA + sB * cB;
    float inv = 1.f / (ssum + 1e-16f);
    float o[8];
    o[0] = (aA0.x*cA + aB0.x*cB) * inv; o[1] = (aA0.y*cA + aB0.y*cB) * inv;
    o[2] = (aA0.z*cA + aB0.z*cB) * inv; o[3] = (aA0.w*cA + aB0.w*cB) * inv;
    o[4] = (aA1.x*cA + aB1.x*cB) * inv; o[5] = (aA1.y*cA + aB1.y*cB) * inv;
    o[6] = (aA1.z*cA + aB1.z*cB) * inv; o[7] = (aA1.w*cA + aB1.w*cB) * inv;

    float rr[8];
    {
        float4 r0 = *reinterpret_cast<const float4*>(&r[(size_t)n * F1 + col]);
        float4 r1 = *reinterpret_cast<const float4*>(&r[(size_t)n * F1 + col + 4]);
        rr[0] = r0.x; rr[1] = r0.y; rr[2] = r0.z; rr[3] = r0.w;
        rr[4] = r1.x; rr[5] = r1.y; rr[6] = r1.z; rr[7] = r1.w;
    }
    float s = 0.f;
#pragma unroll
    for (int u = 0; u < 8; u++) {
        int c = col + u;
        s += o[u] * (wb[c] + wb[2 * F1 + c]) + rr[u] * (wb[F1 + c] - wb[2 * F1 + c]);
    }
#pragma unroll
    for (int off = 16; off > 0; off >>= 1) s += __shfl_xor_sync(0xFFFFFFFFu, s, off);
    float beta = 1.f / (1.f + __expf(-s));
    float res[8];
#pragma unroll
    for (int u = 0; u < 8; u++)
        res[u] = fmaxf(beta * rr[u] + (1.f - beta) * o[u], 0.f);
    *reinterpret_cast<float4*>(&h[(size_t)n * F1 + col]) =
        make_float4(res[0], res[1], res[2], res[3]);
    *reinterpret_cast<float4*>(&h[(size_t)n * F1 + col + 4]) =
        make_float4(res[4], res[5], res[6], res[7]);
}

// ---------------- layer2: attention + beta + log_softmax, ILP2 --------------
__global__ __launch_bounds__(128) void attn2_lsm_kernel(
        const float* __restrict__ q, const float* __restrict__ k,
        const float* __restrict__ v, const float* __restrict__ r,
        const float* __restrict__ wb, float* __restrict__ ob, int dup) {
    int n = (blockIdx.x * blockDim.x + threadIdx.x) >> 5;
    if (n >= N_NODES) return;
    int lane = threadIdx.x & 31;
    int col = lane * 2;

    float2 qv = *reinterpret_cast<const float2*>(&q[(size_t)n * F2 + col]);

    int beg = g_off[n], end = g_off[n + 1];
    float mA = -3.4e38f, sA = 0.f, mB = -3.4e38f, sB = 0.f;
    float aAx = 0.f, aAy = 0.f, aBx = 0.f, aBy = 0.f;

    int i = beg;
    for (; i + 2 <= end; i += 2) {
        int s0 = g_csr_src[i], s1 = g_csr_src[i + 1];
        float2 kA = *reinterpret_cast<const float2*>(&k[(size_t)s0 * F2 + col]);
        float2 kB = *reinterpret_cast<const float2*>(&k[(size_t)s1 * F2 + col]);
        float2 vA = *reinterpret_cast<const float2*>(&v[(size_t)s0 * F2 + col]);
        float2 vB = *reinterpret_cast<const float2*>(&v[(size_t)s1 * F2 + col]);
        float dA = qv.x * kA.x + qv.y * kA.y;
        float dB = qv.x * kB.x + qv.y * kB.y;
#pragma unroll
        for (int o = 16; o > 0; o >>= 1) {
            dA += __shfl_xor_sync(0xFFFFFFFFu, dA, o);
            dB += __shfl_xor_sync(0xFFFFFFFFu, dB, o);
        }
        dA *= 0.125f; dB *= 0.125f;
        float mnA = fmaxf(mA, dA), mnB = fmaxf(mB, dB);
        float cA = __expf(mA - mnA), cB = __expf(mB - mnB);
        float pA = __expf(dA - mnA), pB = __expf(dB - mnB);
        sA = sA * cA + pA; sB = sB * cB + pB;
        aAx = aAx * cA + pA * vA.x; aAy = aAy * cA + pA * vA.y;
        aBx = aBx * cB + pB * vB.x; aBy = aBy * cB + pB * vB.y;
        mA = mnA; mB = mnB;
    }
    if (i < end) {
        int s0 = g_csr_src[i];
        float2 kA = *reinterpret_cast<const float2*>(&k[(size_t)s0 * F2 + col]);
        float2 vA = *reinterpret_cast<const float2*>(&v[(size_t)s0 * F2 + col]);
        float dA = qv.x * kA.x + qv.y * kA.y;
#pragma unroll
        for (int o = 16; o > 0; o >>= 1) dA += __shfl_xor_sync(0xFFFFFFFFu, dA, o);
        dA *= 0.125f;
        float mnA = fmaxf(mA, dA);
        float cA = __expf(mA - mnA), pA = __expf(dA - mnA);
        sA = sA * cA + pA;
        aAx = aAx * cA + pA * vA.x; aAy = aAy * cA + pA * vA.y;
        mA = mnA;
    }
    float mn = fmaxf(mA, mB);
    float cA = __expf(mA - mn), cB = __expf(mB - mn);
    float ssum = sA * cA + sB * cB;
    float inv = 1.f / (ssum + 1e-16f);
    float o0 = (aAx * cA + aBx * cB) * inv;
    float o1 = (aAy * cA + aBy * cB) * inv;

    float r0, r1;
    {
        float2 rv = *reinterpret_cast<const float2*>(&r[(size_t)n * F2 + col]);
        r0 = rv.x; r1 = rv.y;
    }
    float s = o0 * (wb[col] + wb[2 * F2 + col]) + r0 * (wb[F2 + col] - wb[2 * F2 + col])
            + o1 * (wb[col + 1] + wb[2 * F2 + col + 1]) + r1 * (wb[F2 + col + 1] - wb[2 * F2 + col + 1]);
#pragma unroll
    for (int off = 16; off > 0; off >>= 1) s += __shfl_xor_sync(0xFFFFFFFFu, s, off);
    float beta = 1.f / (1.f + __expf(-s));
    float v0 = beta * r0 + (1.f - beta) * o0;
    float v1 = beta * r1 + (1.f - beta) * o1;

    float m = fmaxf(v0, v1);
#pragma unroll
    for (int o = 16; o > 0; o >>= 1) m = fmaxf(m, __shfl_xor_sync(0xFFFFFFFFu, m, o));
    float es = expf(v0 - m) + expf(v1 - m);
#pragma unroll
    for (int o = 16; o > 0; o >>= 1) es += __shfl_xor_sync(0xFFFFFFFFu, es, o);
    float ls = m + logf(es);

    *reinterpret_cast<float2*>(&ob[(size_t)n * F2 + col]) = make_float2(v0 - ls, v1 - ls);
    if (dup) {
        size_t off = (size_t)N_NODES * F2;
        *reinterpret_cast<float2*>(&ob[off + (size_t)n * F2 + col]) = make_float2(v0, v1);
    }
}

// ---------------- host launcher ---------------------------------------------
extern "C" void kernel_launch(void* const* d_in, const int* in_sizes, int n_in,
                              void* d_out, int out_size) {
    const float* x   = (const float*)d_in[0];
    const int*   ei  = (const int*)d_in[1];
    const int*   src = ei;
    const int*   dst = ei + N_EDGES;

    const float* wq1 = (const float*)d_in[3];
    const float* bq1 = (const float*)d_in[4];
    const float* wk1 = (const float*)d_in[5];
    const float* bk1 = (const float*)d_in[6];
    const float* wv1 = (const float*)d_in[7];
    const float* bv1 = (const float*)d_in[8];
    const float* ws1 = (const float*)d_in[9];
    const float* bs1 = (const float*)d_in[10];
    const float* wb1 = (const float*)d_in[11];
    const float* wq2 = (const float*)d_in[12];
    const float* bq2 = (const float*)d_in[13];
    const float* wk2 = (const float*)d_in[14];
    const float* bk2 = (const float*)d_in[15];
    const float* wv2 = (const float*)d_in[16];
    const float* bv2 = (const float*)d_in[17];
    const float* ws2 = (const float*)d_in[18];
    const float* bs2 = (const float*)d_in[19];
    const float* wb2 = (const float*)d_in[20];

    float *q1, *k1, *v1, *r1, *h;
    float *q2, *k2, *v2, *r2;
    float *bt1, *bt2;
    int *degp;
    cudaGetSymbolAddress((void**)&q1, g_q1);
    cudaGetSymbolAddress((void**)&k1, g_k1);
    cudaGetSymbolAddress((void**)&v1, g_v1);
    cudaGetSymbolAddress((void**)&r1, g_r1);
    cudaGetSymbolAddress((void**)&h, g_h);
    cudaGetSymbolAddress((void**)&q2, g_q2);
    cudaGetSymbolAddress((void**)&k2, g_k2);
    cudaGetSymbolAddress((void**)&v2, g_v2);
    cudaGetSymbolAddress((void**)&r2, g_r2);
    cudaGetSymbolAddress((void**)&bt1, g_btile1);
    cudaGetSymbolAddress((void**)&bt2, g_btile2);
    cudaGetSymbolAddress((void**)&degp, g_deg);

    cudaFuncSetAttribute(gemm4_tf32, cudaFuncAttributeMaxDynamicSharedMemorySize,
                         GEMM_SMEM);

    cudaStream_t s2;
    cudaEvent_t evFork, evCsr, evA0, evG0;
    cudaStreamCreateWithFlags(&s2, cudaStreamNonBlocking);
    cudaEventCreateWithFlags(&evFork, cudaEventDisableTiming);
    cudaEventCreateWithFlags(&evCsr, cudaEventDisableTiming);
    cudaEventCreateWithFlags(&evA0, cudaEventDisableTiming);
    cudaEventCreateWithFlags(&evG0, cudaEventDisableTiming);

    cudaEventRecord(evFork, 0);
    cudaStreamWaitEvent(s2, evFork, 0);

    // side stream: CSR build (overlaps layer-1 GEMM)
    cudaMemsetAsync(degp, 0, N_NODES * sizeof(int), s2);
    deg_count_kernel<<<(N_EDGES + 255) / 256, 256, 0, s2>>>(dst);
    scan1_kernel<<<SCAN_NBLK, 256, 0, s2>>>();
    scan2_kernel<<<1, 64, 0, s2>>>();
    scan3_kernel<<<SCAN_NBLK, 256, 0, s2>>>();
    scatter_kernel<<<(N_EDGES + 255) / 256, 256, 0, s2>>>(src, dst);
    cudaEventRecord(evCsr, s2);

    // main stream: both bias tiles early, then layer-1 GEMM (full)
    btile_kernel<<<(4 * 16 * F1 + 255) / 256, 256>>>(bq1, bk1, bv1, bs1, bt1, F1);
    btile_kernel<<<(4 * 16 * F2 + 255) / 256, 256>>>(bq2, bk2, bv2, bs2, bt2, F2);
    dim3 g1(F1 / 64, (N_NODES + 127) / 128, 4);
    gemm4_tf32<<<g1, 128, GEMM_SMEM>>>(x, wq1, wk1, wv1, ws1, q1, k1, v1, r1,
                                       bt1, N_NODES, F1, IN_CH);

    // attn1 chunk 0 (needs CSR + GEMM1)
    cudaStreamWaitEvent(0, evCsr, 0);
    attn1_beta_kernel<<<(CHUNK0 + 3) / 4, 128>>>(q1, k1, v1, r1, wb1, h,
                                                 0, CHUNK0);
    cudaEventRecord(evA0, 0);

    // side stream: layer-2 GEMM on chunk-0 rows, concurrent with attn1 chunk 1
    cudaStreamWaitEvent(s2, evA0, 0);
    {
        dim3 g2a(F2 / 64, CHUNK0 / 128, 4);
        gemm4_tf32<<<g2a, 128, GEMM_SMEM, s2>>>(
            h, wq2, wk2, wv2, ws2, q2, k2, v2, r2, bt2, CHUNK0, F2, F1);
    }
    cudaEventRecord(evG0, s2);

    // main stream: attn1 chunk 1
    attn1_beta_kernel<<<(CHUNK1 + 3) / 4, 128>>>(q1, k1, v1, r1, wb1, h,
                                                 CHUNK0, CHUNK1);

    // main stream: layer-2 GEMM on chunk-1 rows
    {
        size_t ro = (size_t)CHUNK0;
        dim3 g2b(F2 / 64, (CHUNK1 + 127) / 128, 4);
        gemm4_tf32<<<g2b, 128, GEMM_SMEM>>>(
            h + ro * F1, wq2, wk2, wv2, ws2,
            q2 + ro * F2, k2 + ro * F2, v2 + ro * F2, r2 + ro * F2,
            bt2, CHUNK1, F2, F1);
    }

    // join: attn2 needs both gemm2 chunks
    cudaStreamWaitEvent(0, evG0, 0);
    int dup = (out_size >= 2 * N_NODES * F2) ? 1 : 0;
    attn2_lsm_kernel<<<(N_NODES + 3) / 4, 128>>>(q2, k2, v2, r2, wb2,
                                                 (float*)d_out, dup);

    cudaEventDestroy(evFork);
    cudaEventDestroy(evCsr);
    cudaEventDestroy(evA0);
    cudaEventDestroy(evG0);
    cudaStreamDestroy(s2);
}

// round 10
// speedup vs baseline: 1.1573x; 1.1573x over previous
#include <cuda_runtime.h>
#include <cuda_bf16.h>
#include <mma.h>
#include <math.h>
#include <stdint.h>

using namespace nvcuda;

#define N_NODES 50000
#define N_EDGES 800000
#define IN_CH   128
#define F1      256   // heads*out layer1
#define F2      64
#define H1      4
#define KV_LD   512   // interleaved kv row: k[0:256) | v[256:512), bf16

// ---------------- scratch (device globals; no allocation allowed) -----------
__device__ float g_q1[N_NODES * F1];
__device__ float g_r1[N_NODES * F1];
__device__ float g_h[N_NODES * F1];
__device__ uint4 g_kv1[N_NODES * KV_LD / 8];   // bf16 kv, 16B-aligned

__device__ float g_q2[N_NODES * F2];
__device__ float g_k2[N_NODES * F2];
__device__ float g_v2[N_NODES * F2];
__device__ float g_r2[N_NODES * F2];

__device__ float g_btile1[4 * 16 * F1];
__device__ float g_btile2[4 * 16 * F2];

// CSR scratch
#define SCAN_NBLK ((N_NODES + 1023) / 1024)   // 49
__device__ int g_deg[N_NODES];
__device__ int g_off[N_NODES + 1];
__device__ int g_pos[N_NODES];
__device__ int g_csr_src[N_EDGES];
__device__ int g_bsum[SCAN_NBLK];
__device__ int g_bscan[SCAN_NBLK];

// ---------------- cp.async helpers ------------------------------------------
__device__ __forceinline__ void cp_async16(uint32_t saddr, const void* gptr) {
    asm volatile("cp.async.cg.shared.global [%0], [%1], 16;\n"
                 :: "r"(saddr), "l"(gptr));
}
__device__ __forceinline__ void cp_commit() {
    asm volatile("cp.async.commit_group;\n");
}
template <int N>
__device__ __forceinline__ void cp_wait() {
    asm volatile("cp.async.wait_group %0;\n" :: "n"(N));
}

// ---------------- CSR build --------------------------------------------------
__global__ void zero_deg_kernel() {
    int i = blockIdx.x * blockDim.x + threadIdx.x;
    if (i < N_NODES) g_deg[i] = 0;
}

__global__ void deg_count_kernel(const int* __restrict__ dst) {
    int e = blockIdx.x * blockDim.x + threadIdx.x;
    if (e < N_EDGES) atomicAdd(&g_deg[dst[e]], 1);
}

__global__ void scan1_kernel() {
    __shared__ int ss[256];
    int t = threadIdx.x;
    int base = blockIdx.x * 1024 + t * 4;
    int d0 = (base     < N_NODES) ? g_deg[base]     : 0;
    int d1 = (base + 1 < N_NODES) ? g_deg[base + 1] : 0;
    int d2 = (base + 2 < N_NODES) ? g_deg[base + 2] : 0;
    int d3 = (base + 3 < N_NODES) ? g_deg[base + 3] : 0;
    int s = d0 + d1 + d2 + d3;
    ss[t] = s;
    __syncthreads();
    for (int off = 1; off < 256; off <<= 1) {
        int v = (t >= off) ? ss[t - off] : 0;
        __syncthreads();
        ss[t] += v;
        __syncthreads();
    }
    int ex = ss[t] - s;
    int e0 = ex, e1 = ex + d0, e2 = e1 + d1, e3 = e2 + d2;
    if (base     < N_NODES) g_off[base]     = e0;
    if (base + 1 < N_NODES) g_off[base + 1] = e1;
    if (base + 2 < N_NODES) g_off[base + 2] = e2;
    if (base + 3 < N_NODES) g_off[base + 3] = e3;
    if (t == 255) g_bsum[blockIdx.x] = ss[255];
}

__global__ void scan2_kernel() {
    __shared__ int ss[64];
    int t = threadIdx.x;
    int v = (t < SCAN_NBLK) ? g_bsum[t] : 0;
    ss[t] = v;
    __syncthreads();
    for (int off = 1; off < 64; off <<= 1) {
        int u = (t >= off) ? ss[t - off] : 0;
        __syncthreads();
        ss[t] += u;
        __syncthreads();
    }
    if (t < SCAN_NBLK) g_bscan[t] = ss[t] - v;
    if (t == SCAN_NBLK - 1) g_off[N_NODES] = ss[t];
}

__global__ void scan3_kernel() {
    int t = threadIdx.x;
    int add = g_bscan[blockIdx.x];
    int base = blockIdx.x * 1024 + t * 4;
#pragma unroll
    for (int i = 0; i < 4; i++) {
        int idx = base + i;
        if (idx < N_NODES) {
            int v = g_off[idx] + add;
            g_off[idx] = v;
            g_pos[idx] = v;
        }
    }
}

__global__ void scatter_kernel(const int* __restrict__ src, const int* __restrict__ dst) {
    int e = blockIdx.x * blockDim.x + threadIdx.x;
    if (e < N_EDGES) {
        int slot = atomicAdd(&g_pos[dst[e]], 1);
        g_csr_src[slot] = src[e];
    }
}

// ---------------- bias tile: 16 identical rows per GEMM ----------------------
__global__ void btile_kernel(const float* __restrict__ b0, const float* __restrict__ b1,
                             const float* __restrict__ b2, const float* __restrict__ b3,
                             float* __restrict__ out, int Nn) {
    int i = blockIdx.x * blockDim.x + threadIdx.x;
    int total = 4 * 16 * Nn;
    if (i >= total) return;
    int z = i / (16 * Nn);
    int c = i % Nn;
    const float* b = (z == 0) ? b0 : (z == 1) ? b1 : (z == 2) ? b2 : b3;
    out[i] = b[c];
}

// ---------------- TF32 GEMM + bias, BK=32, 4 warps, 64x32 warp tile ----------
// C_z = A @ B_z + bias_z. If bf16mask bit z set, output is converted to bf16
// and written into kvOut at column offset (z==1 ? 0 : 256), row stride KV_LD.
#define GEMM_SMEM ((2 * 128 * 36 + 2 * 32 * 68) * 4)   // 54272 bytes

__global__ __launch_bounds__(128) void gemm4_tf32(
        const float* __restrict__ A,
        const float* __restrict__ B0, const float* __restrict__ B1,
        const float* __restrict__ B2, const float* __restrict__ B3,
        float* __restrict__ C0, float* __restrict__ C1,
        float* __restrict__ C2, float* __restrict__ C3,
        __nv_bfloat16* __restrict__ kvOut,
        const float* __restrict__ btile,
        int M, int Nn, int K, int bf16mask) {
    const float* B;
    float* C;
    switch (blockIdx.z) {
        case 0: B = B0; C = C0; break;
        case 1: B = B1; C = C1; break;
        case 2: B = B2; C = C2; break;
        default: B = B3; C = C3; break;
    }
    const float* biasT = btile + (size_t)blockIdx.z * 16 * Nn;
    bool toBf16 = (bf16mask >> blockIdx.z) & 1;

    extern __shared__ float dsm[];
    float (*As)[128][36] = reinterpret_cast<float(*)[128][36]>(dsm);
    float (*Bs)[32][68]  = reinterpret_cast<float(*)[32][68]>(dsm + 2 * 128 * 36);

    int tid = threadIdx.x;
    int warp = tid >> 5;
    int wm = warp & 1;
    int wn = warp >> 1;
    int rowBase = blockIdx.y * 128;
    int colBase = blockIdx.x * 64;

    int aRow = tid >> 3;
    int aCol = (tid & 7) * 4;
    int bRow = tid >> 4;
    int bCol = (tid & 15) * 4;

    int grA[8];
#pragma unroll
    for (int r = 0; r < 8; r++) {
        int rr = rowBase + aRow + r * 16;
        grA[r] = rr < M ? rr : M - 1;
    }

    uint32_t aBase[2], bBase[2];
#pragma unroll
    for (int st = 0; st < 2; st++) {
        aBase[st] = (uint32_t)__cvta_generic_to_shared(&As[st][aRow][aCol]);
        bBase[st] = (uint32_t)__cvta_generic_to_shared(&Bs[st][bRow][bCol]);
    }

    wmma::fragment<wmma::accumulator, 16, 16, 8, float> acc[4][2];
#pragma unroll
    for (int i = 0; i < 4; i++)
#pragma unroll
        for (int j = 0; j < 2; j++)
            wmma::load_matrix_sync(acc[i][j], &biasT[colBase + wn * 32 + j * 16],
                                   Nn, wmma::mem_row_major);

#pragma unroll
    for (int r = 0; r < 8; r++)
        cp_async16(aBase[0] + r * (16 * 36 * 4), &A[(size_t)grA[r] * K + aCol]);
#pragma unroll
    for (int r = 0; r < 4; r++)
        cp_async16(bBase[0] + r * (8 * 68 * 4),
                   &B[(size_t)(bRow + r * 8) * Nn + colBase + bCol]);
    cp_commit();

    int st = 0;
    for (int k0 = 0; k0 < K; k0 += 32) {
        if (k0 + 32 < K) {
            int ns = st ^ 1;
#pragma unroll
            for (int r = 0; r < 8; r++)
                cp_async16(aBase[ns] + r * (16 * 36 * 4),
                           &A[(size_t)grA[r] * K + k0 + 32 + aCol]);
#pragma unroll
            for (int r = 0; r < 4; r++)
                cp_async16(bBase[ns] + r * (8 * 68 * 4),
                           &B[(size_t)(k0 + 32 + bRow + r * 8) * Nn + colBase + bCol]);
        }
        cp_commit();
        cp_wait<1>();
        __syncthreads();

#pragma unroll
        for (int ks = 0; ks < 32; ks += 8) {
            wmma::fragment<wmma::matrix_a, 16, 16, 8, wmma::precision::tf32, wmma::row_major> af[4];
            wmma::fragment<wmma::matrix_b, 16, 16, 8, wmma::precision::tf32, wmma::row_major> bf[2];
#pragma unroll
            for (int i = 0; i < 4; i++) {
                wmma::load_matrix_sync(af[i], &As[st][wm * 64 + i * 16][ks], 36);
#pragma unroll
                for (int t = 0; t < af[i].num_elements; t++)
                    af[i].x[t] = wmma::__float_to_tf32(af[i].x[t]);
            }
#pragma unroll
            for (int j = 0; j < 2; j++) {
                wmma::load_matrix_sync(bf[j], &Bs[st][ks][wn * 32 + j * 16], 68);
#pragma unroll
                for (int t = 0; t < bf[j].num_elements; t++)
                    bf[j].x[t] = wmma::__float_to_tf32(bf[j].x[t]);
            }
#pragma unroll
            for (int i = 0; i < 4; i++)
#pragma unroll
                for (int j = 0; j < 2; j++)
                    wmma::mma_sync(acc[i][j], af[i], bf[j], acc[i][j]);
        }
        __syncthreads();
        st ^= 1;
    }

    if (!toBf16) {
#pragma unroll
        for (int i = 0; i < 4; i++) {
            int r = rowBase + wm * 64 + i * 16;
            if (r < M) {   // M % 16 == 0 -> fragment fully valid
#pragma unroll
                for (int j = 0; j < 2; j++)
                    wmma::store_matrix_sync(&C[(size_t)r * Nn + colBase + wn * 32 + j * 16],
                                            acc[i][j], Nn, wmma::mem_row_major);
            }
        }
    } else {
        // stage fp32 tile in smem, convert to bf16, write interleaved kv rows
        float (*stage)[64] = reinterpret_cast<float(*)[64]>(dsm);
#pragma unroll
        for (int i = 0; i < 4; i++)
#pragma unroll
            for (int j = 0; j < 2; j++)
                wmma::store_matrix_sync(&stage[wm * 64 + i * 16][wn * 32 + j * 16],
                                        acc[i][j], 64, wmma::mem_row_major);
        __syncthreads();
        int kvoff = (blockIdx.z == 1) ? 0 : 256;
#pragma unroll
        for (int pass = 0; pass < 8; pass++) {
            int row = pass * 16 + (tid >> 3);
            int c8 = (tid & 7) * 8;
            int gr = rowBase + row;
            if (gr < M) {
                const float* sp = &stage[row][c8];
                __nv_bfloat162 o0 = __float22bfloat162_rn(make_float2(sp[0], sp[1]));
                __nv_bfloat162 o1 = __float22bfloat162_rn(make_float2(sp[2], sp[3]));
                __nv_bfloat162 o2 = __float22bfloat162_rn(make_float2(sp[4], sp[5]));
                __nv_bfloat162 o3 = __float22bfloat162_rn(make_float2(sp[6], sp[7]));
                uint4 out;
                out.x = *reinterpret_cast<uint32_t*>(&o0);
                out.y = *reinterpret_cast<uint32_t*>(&o1);
                out.z = *reinterpret_cast<uint32_t*>(&o2);
                out.w = *reinterpret_cast<uint32_t*>(&o3);
                *reinterpret_cast<uint4*>(
                    &kvOut[(size_t)gr * KV_LD + kvoff + colBase + c8]) = out;
            }
        }
    }
}

// ---------------- layer1: attention + beta + relu, warp per node, ILP2 ------
// kv: interleaved bf16 rows (k | v), biases folded in by GEMM.
__global__ __launch_bounds__(128) void attn1_beta_kernel(
        const float* __restrict__ q, const __nv_bfloat16* __restrict__ kv,
        const float* __restrict__ r, const float* __restrict__ wb,
        float* __restrict__ h) {
    int n = (blockIdx.x * blockDim.x + threadIdx.x) >> 5;
    if (n >= N_NODES) return;
    int lane = threadIdx.x & 31;
    int col = lane * 8;

    float4 q0 = *reinterpret_cast<const float4*>(&q[(size_t)n * F1 + col]);
    float4 q1 = *reinterpret_cast<const float4*>(&q[(size_t)n * F1 + col + 4]);

    int beg = g_off[n], end = g_off[n + 1];

    float mA = -3.4e38f, sA = 0.f, mB = -3.4e38f, sB = 0.f;
    float4 aA0 = {0,0,0,0}, aA1 = {0,0,0,0}, aB0 = {0,0,0,0}, aB1 = {0,0,0,0};

    int i = beg;
    for (; i + 2 <= end; i += 2) {
        int s0 = g_csr_src[i], s1 = g_csr_src[i + 1];
        size_t b0 = (size_t)s0 * KV_LD + col, b1 = (size_t)s1 * KV_LD + col;
        uint4 krA = *reinterpret_cast<const uint4*>(kv + b0);
        uint4 vrA = *reinterpret_cast<const uint4*>(kv + b0 + 256);
        uint4 krB = *reinterpret_cast<const uint4*>(kv + b1);
        uint4 vrB = *reinterpret_cast<const uint4*>(kv + b1 + 256);

        float2 kA0 = __bfloat1622float2(*reinterpret_cast<__nv_bfloat162*>(&krA.x));
        float2 kA1 = __bfloat1622float2(*reinterpret_cast<__nv_bfloat162*>(&krA.y));
        float2 kA2 = __bfloat1622float2(*reinterpret_cast<__nv_bfloat162*>(&krA.z));
        float2 kA3 = __bfloat1622float2(*reinterpret_cast<__nv_bfloat162*>(&krA.w));
        float2 kB0 = __bfloat1622float2(*reinterpret_cast<__nv_bfloat162*>(&krB.x));
        float2 kB1 = __bfloat1622float2(*reinterpret_cast<__nv_bfloat162*>(&krB.y));
        float2 kB2 = __bfloat1622float2(*reinterpret_cast<__nv_bfloat162*>(&krB.z));
        float2 kB3 = __bfloat1622float2(*reinterpret_cast<__nv_bfloat162*>(&krB.w));

        float dA = q0.x*kA0.x + q0.y*kA0.y + q0.z*kA1.x + q0.w*kA1.y
                 + q1.x*kA2.x + q1.y*kA2.y + q1.z*kA3.x + q1.w*kA3.y;
        float dB = q0.x*kB0.x + q0.y*kB0.y + q0.z*kB1.x + q0.w*kB1.y
                 + q1.x*kB2.x + q1.y*kB2.y + q1.z*kB3.x + q1.w*kB3.y;
        dA += __shfl_xor_sync(0xFFFFFFFFu, dA, 1);
        dB += __shfl_xor_sync(0xFFFFFFFFu, dB, 1);
        dA += __shfl_xor_sync(0xFFFFFFFFu, dA, 2);
        dB += __shfl_xor_sync(0xFFFFFFFFu, dB, 2);
        dA += __shfl_xor_sync(0xFFFFFFFFu, dA, 4);
        dB += __shfl_xor_sync(0xFFFFFFFFu, dB, 4);
        dA *= 0.125f; dB *= 0.125f;

        float2 vA0 = __bfloat1622float2(*reinterpret_cast<__nv_bfloat162*>(&vrA.x));
        float2 vA1 = __bfloat1622float2(*reinterpret_cast<__nv_bfloat162*>(&vrA.y));
        float2 vA2 = __bfloat1622float2(*reinterpret_cast<__nv_bfloat162*>(&vrA.z));
        float2 vA3 = __bfloat1622float2(*reinterpret_cast<__nv_bfloat162*>(&vrA.w));
        float2 vB0 = __bfloat1622float2(*reinterpret_cast<__nv_bfloat162*>(&vrB.x));
        float2 vB1 = __bfloat1622float2(*reinterpret_cast<__nv_bfloat162*>(&vrB.y));
        float2 vB2 = __bfloat1622float2(*reinterpret_cast<__nv_bfloat162*>(&vrB.z));
        float2 vB3 = __bfloat1622float2(*reinterpret_cast<__nv_bfloat162*>(&vrB.w));

        float mnA = fmaxf(mA, dA), mnB = fmaxf(mB, dB);
        float cA = __expf(mA - mnA), cB = __expf(mB - mnB);
        float pA = __expf(dA - mnA), pB = __expf(dB - mnB);
        sA = sA * cA + pA; sB = sB * cB + pB;
        aA0.x = aA0.x*cA + pA*vA0.x; aA0.y = aA0.y*cA + pA*vA0.y;
        aA0.z = aA0.z*cA + pA*vA1.x; aA0.w = aA0.w*cA + pA*vA1.y;
        aA1.x = aA1.x*cA + pA*vA2.x; aA1.y = aA1.y*cA + pA*vA2.y;
        aA1.z = aA1.z*cA + pA*vA3.x; aA1.w = aA1.w*cA + pA*vA3.y;
        aB0.x = aB0.x*cB + pB*vB0.x; aB0.y = aB0.y*cB + pB*vB0.y;
        aB0.z = aB0.z*cB + pB*vB1.x; aB0.w = aB0.w*cB + pB*vB1.y;
        aB1.x = aB1.x*cB + pB*vB2.x; aB1.y = aB1.y*cB + pB*vB2.y;
        aB1.z = aB1.z*cB + pB*vB3.x; aB1.w = aB1.w*cB + pB*vB3.y;
        mA = mnA; mB = mnB;
    }
    if (i < end) {
        int s0 = g_csr_src[i];
        size_t b0 = (size_t)s0 * KV_LD + col;
        uint4 krA = *reinterpret_cast<const uint4*>(kv + b0);
        uint4 vrA = *reinterpret_cast<const uint4*>(kv + b0 + 256);
        float2 kA0 = __bfloat1622float2(*reinterpret_cast<__nv_bfloat162*>(&krA.x));
        float2 kA1 = __bfloat1622float2(*reinterpret_cast<__nv_bfloat162*>(&krA.y));
        float2 kA2 = __bfloat1622float2(*reinterpret_cast<__nv_bfloat162*>(&krA.z));
        float2 kA3 = __bfloat1622float2(*reinterpret_cast<__nv_bfloat162*>(&krA.w));
        float dA = q0.x*kA0.x + q0.y*kA0.y + q0.z*kA1.x + q0.w*kA1.y
                 + q1.x*kA2.x + q1.y*kA2.y + q1.z*kA3.x + q1.w*kA3.y;
        dA += __shfl_xor_sync(0xFFFFFFFFu, dA, 1);
        dA += __shfl_xor_sync(0xFFFFFFFFu, dA, 2);
        dA += __shfl_xor_sync(0xFFFFFFFFu, dA, 4);
        dA *= 0.125f;
        float2 vA0 = __bfloat1622float2(*reinterpret_cast<__nv_bfloat162*>(&vrA.x));
        float2 vA1 = __bfloat1622float2(*reinterpret_cast<__nv_bfloat162*>(&vrA.y));
        float2 vA2 = __bfloat1622float2(*reinterpret_cast<__nv_bfloat162*>(&vrA.z));
        float2 vA3 = __bfloat1622float2(*reinterpret_cast<__nv_bfloat162*>(&vrA.w));
        float mnA = fmaxf(mA, dA);
        float cA = __expf(mA - mnA), pA = __expf(dA - mnA);
        sA = sA * cA + pA;
        aA0.x = aA0.x*cA + pA*vA0.x; aA0.y = aA0.y*cA + pA*vA0.y;
        aA0.z = aA0.z*cA + pA*vA1.x; aA0.w = aA0.w*cA + pA*vA1.y;
        aA1.x = aA1.x*cA + pA*vA2.x; aA1.y = aA1.y*cA + pA*vA2.y;
        aA1.z = aA1.z*cA + pA*vA3.x; aA1.w = aA1.w*cA + pA*vA3.y;
        mA = mnA;
    }
    float mn = fmaxf(mA, mB);
    float cA = __expf(mA - mn), cB = __expf(mB - mn);
    float ssum = sA * cA + sB * cB;
    float inv = 1.f / (ssum + 1e-16f);
    float o[8];
    o[0] = (aA0.x*cA + aB0.x*cB) * inv; o[1] = (aA0.y*cA + aB0.y*cB) * inv;
    o[2] = (aA0.z*cA + aB0.z*cB) * inv; o[3] = (aA0.w*cA + aB0.w*cB) * inv;
    o[4] = (aA1.x*cA + aB1.x*cB) * inv; o[5] = (aA1.y*cA + aB1.y*cB) * inv;
    o[6] = (aA1.z*cA + aB1.z*cB) * inv; o[7] = (aA1.w*cA + aB1.w*cB) * inv;

    float rr[8];
    {
        float4 r0 = *reinterpret_cast<const float4*>(&r[(size_t)n * F1 + col]);
        float4 r1 = *reinterpret_cast<const float4*>(&r[(size_t)n * F1 + col + 4]);
        rr[0] = r0.x; rr[1] = r0.y; rr[2] = r0.z; rr[3] = r0.w;
        rr[4] = r1.x; rr[5] = r1.y; rr[6] = r1.z; rr[7] = r1.w;
    }
    float s = 0.f;
#pragma unroll
    for (int u = 0; u < 8; u++) {
        int c = col + u;
        s += o[u] * (wb[c] + wb[2 * F1 + c]) + rr[u] * (wb[F1 + c] - wb[2 * F1 + c]);
    }
#pragma unroll
    for (int off = 16; off > 0; off >>= 1) s += __shfl_xor_sync(0xFFFFFFFFu, s, off);
    float beta = 1.f / (1.f + __expf(-s));
    float res[8];
#pragma unroll
    for (int u = 0; u < 8; u++)
        res[u] = fmaxf(beta * rr[u] + (1.f - beta) * o[u], 0.f);
    *reinterpret_cast<float4*>(&h[(size_t)n * F1 + col]) =
        make_float4(res[0], res[1], res[2], res[3]);
    *reinterpret_cast<float4*>(&h[(size_t)n * F1 + col + 4]) =
        make_float4(res[4], res[5], res[6], res[7]);
}

// ---------------- layer2: attention + beta + log_softmax, ILP2 (fp32) -------
__global__ __launch_bounds__(128) void attn2_lsm_kernel(
        const float* __restrict__ q, const float* __restrict__ k,
        const float* __restrict__ v, const float* __restrict__ r,
        const float* __restrict__ wb, float* __restrict__ ob, int dup) {
    int n = (blockIdx.x * blockDim.x + threadIdx.x) >> 5;
    if (n >= N_NODES) return;
    int lane = threadIdx.x & 31;
    int col = lane * 2;

    float2 qv = *reinterpret_cast<const float2*>(&q[(size_t)n * F2 + col]);

    int beg = g_off[n], end = g_off[n + 1];
    float mA = -3.4e38f, sA = 0.f, mB = -3.4e38f, sB = 0.f;
    float aAx = 0.f, aAy = 0.f, aBx = 0.f, aBy = 0.f;

    int i = beg;
    for (; i + 2 <= end; i += 2) {
        int s0 = g_csr_src[i], s1 = g_csr_src[i + 1];
        float2 kA = *reinterpret_cast<const float2*>(&k[(size_t)s0 * F2 + col]);
        float2 kB = *reinterpret_cast<const float2*>(&k[(size_t)s1 * F2 + col]);
        float2 vA = *reinterpret_cast<const float2*>(&v[(size_t)s0 * F2 + col]);
        float2 vB = *reinterpret_cast<const float2*>(&v[(size_t)s1 * F2 + col]);
        float dA = qv.x * kA.x + qv.y * kA.y;
        float dB = qv.x * kB.x + qv.y * kB.y;
#pragma unroll
        for (int o = 16; o > 0; o >>= 1) {
            dA += __shfl_xor_sync(0xFFFFFFFFu, dA, o);
            dB += __shfl_xor_sync(0xFFFFFFFFu, dB, o);
        }
        dA *= 0.125f; dB *= 0.125f;
        float mnA = fmaxf(mA, dA), mnB = fmaxf(mB, dB);
        float cA = __expf(mA - mnA), cB = __expf(mB - mnB);
        float pA = __expf(dA - mnA), pB = __expf(dB - mnB);
        sA = sA * cA + pA; sB = sB * cB + pB;
        aAx = aAx * cA + pA * vA.x; aAy = aAy * cA + pA * vA.y;
        aBx = aBx * cB + pB * vB.x; aBy = aBy * cB + pB * vB.y;
        mA = mnA; mB = mnB;
    }
    if (i < end) {
        int s0 = g_csr_src[i];
        float2 kA = *reinterpret_cast<const float2*>(&k[(size_t)s0 * F2 + col]);
        float2 vA = *reinterpret_cast<const float2*>(&v[(size_t)s0 * F2 + col]);
        float dA = qv.x * kA.x + qv.y * kA.y;
#pragma unroll
        for (int o = 16; o > 0; o >>= 1) dA += __shfl_xor_sync(0xFFFFFFFFu, dA, o);
        dA *= 0.125f;
        float mnA = fmaxf(mA, dA);
        float cA = __expf(mA - mnA), pA = __expf(dA - mnA);
        sA = sA * cA + pA;
        aAx = aAx * cA + pA * vA.x; aAy = aAy * cA + pA * vA.y;
        mA = mnA;
    }
    float mn = fmaxf(mA, mB);
    float cA = __expf(mA - mn), cB = __expf(mB - mn);
    float ssum = sA * cA + sB * cB;
    float inv = 1.f / (ssum + 1e-16f);
    float o0 = (aAx * cA + aBx * cB) * inv;
    float o1 = (aAy * cA + aBy * cB) * inv;

    float r0, r1;
    {
        float2 rv = *reinterpret_cast<const float2*>(&r[(size_t)n * F2 + col]);
        r0 = rv.x; r1 = rv.y;
    }
    float s = o0 * (wb[col] + wb[2 * F2 + col]) + r0 * (wb[F2 + col] - wb[2 * F2 + col])
            + o1 * (wb[col + 1] + wb[2 * F2 + col + 1]) + r1 * (wb[F2 + col + 1] - wb[2 * F2 + col + 1]);
#pragma unroll
    for (int off = 16; off > 0; off >>= 1) s += __shfl_xor_sync(0xFFFFFFFFu, s, off);
    float beta = 1.f / (1.f + __expf(-s));
    float v0 = beta * r0 + (1.f - beta) * o0;
    float v1 = beta * r1 + (1.f - beta) * o1;

    float m = fmaxf(v0, v1);
#pragma unroll
    for (int o = 16; o > 0; o >>= 1) m = fmaxf(m, __shfl_xor_sync(0xFFFFFFFFu, m, o));
    float es = expf(v0 - m) + expf(v1 - m);
#pragma unroll
    for (int o = 16; o > 0; o >>= 1) es += __shfl_xor_sync(0xFFFFFFFFu, es, o);
    float ls = m + logf(es);

    *reinterpret_cast<float2*>(&ob[(size_t)n * F2 + col]) = make_float2(v0 - ls, v1 - ls);
    if (dup) {
        size_t off = (size_t)N_NODES * F2;
        *reinterpret_cast<float2*>(&ob[off + (size_t)n * F2 + col]) = make_float2(v0, v1);
    }
}

// ---------------- host launcher ---------------------------------------------
extern "C" void kernel_launch(void* const* d_in, const int* in_sizes, int n_in,
                              void* d_out, int out_size) {
    const float* x   = (const float*)d_in[0];
    const int*   ei  = (const int*)d_in[1];
    const int*   src = ei;
    const int*   dst = ei + N_EDGES;

    const float* wq1 = (const float*)d_in[3];
    const float* bq1 = (const float*)d_in[4];
    const float* wk1 = (const float*)d_in[5];
    const float* bk1 = (const float*)d_in[6];
    const float* wv1 = (const float*)d_in[7];
    const float* bv1 = (const float*)d_in[8];
    const float* ws1 = (const float*)d_in[9];
    const float* bs1 = (const float*)d_in[10];
    const float* wb1 = (const float*)d_in[11];
    const float* wq2 = (const float*)d_in[12];
    const float* bq2 = (const float*)d_in[13];
    const float* wk2 = (const float*)d_in[14];
    const float* bk2 = (const float*)d_in[15];
    const float* wv2 = (const float*)d_in[16];
    const float* bv2 = (const float*)d_in[17];
    const float* ws2 = (const float*)d_in[18];
    const float* bs2 = (const float*)d_in[19];
    const float* wb2 = (const float*)d_in[20];

    float *q1, *r1, *h;
    float *q2, *k2, *v2, *r2;
    float *bt1, *bt2;
    __nv_bfloat16 *kv1;
    cudaGetSymbolAddress((void**)&q1, g_q1);
    cudaGetSymbolAddress((void**)&r1, g_r1);
    cudaGetSymbolAddress((void**)&h, g_h);
    cudaGetSymbolAddress((void**)&kv1, g_kv1);
    cudaGetSymbolAddress((void**)&q2, g_q2);
    cudaGetSymbolAddress((void**)&k2, g_k2);
    cudaGetSymbolAddress((void**)&v2, g_v2);
    cudaGetSymbolAddress((void**)&r2, g_r2);
    cudaGetSymbolAddress((void**)&bt1, g_btile1);
    cudaGetSymbolAddress((void**)&bt2, g_btile2);

    cudaFuncSetAttribute(gemm4_tf32, cudaFuncAttributeMaxDynamicSharedMemorySize,
                         GEMM_SMEM);

    cudaStream_t s2;
    cudaEvent_t evFork, evCsr;
    cudaStreamCreateWithFlags(&s2, cudaStreamNonBlocking);
    cudaEventCreateWithFlags(&evFork, cudaEventDisableTiming);
    cudaEventCreateWithFlags(&evCsr, cudaEventDisableTiming);

    cudaEventRecord(evFork, 0);
    cudaStreamWaitEvent(s2, evFork, 0);

    // side stream: CSR build (overlaps layer-1 GEMM)
    zero_deg_kernel<<<(N_NODES + 255) / 256, 256, 0, s2>>>();
    btile_kernel<<<(4 * 16 * F1 + 255) / 256, 256>>>(bq1, bk1, bv1, bs1, bt1, F1);
    btile_kernel<<<(4 * 16 * F2 + 255) / 256, 256>>>(bq2, bk2, bv2, bs2, bt2, F2);
    deg_count_kernel<<<(N_EDGES + 255) / 256, 256, 0, s2>>>(dst);
    scan1_kernel<<<SCAN_NBLK, 256, 0, s2>>>();

    // main stream: layer-1 GEMM (q fp32, k/v -> bf16 kv, r fp32)
    dim3 g1(F1 / 64, (N_NODES + 127) / 128, 4);
    gemm4_tf32<<<g1, 128, GEMM_SMEM>>>(x, wq1, wk1, wv1, ws1,
                                       q1, q1, q1, r1,   // C1/C2 unused (bf16 path)
                                       kv1, bt1, N_NODES, F1, IN_CH, 0b0110);

    scan2_kernel<<<1, 64, 0, s2>>>();
    scan3_kernel<<<SCAN_NBLK, 256, 0, s2>>>();
    scatter_kernel<<<(N_EDGES + 255) / 256, 256, 0, s2>>>(src, dst);
    cudaEventRecord(evCsr, s2);

    // join: attn1 needs CSR + GEMM1
    cudaStreamWaitEvent(0, evCsr, 0);
    attn1_beta_kernel<<<(N_NODES + 3) / 4, 128>>>(q1, kv1, r1, wb1, h);

    // layer 2 (all fp32)
    dim3 g2(F2 / 64, (N_NODES + 127) / 128, 4);
    gemm4_tf32<<<g2, 128, GEMM_SMEM>>>(h, wq2, wk2, wv2, ws2,
                                       q2, k2, v2, r2,
                                       kv1, bt2, N_NODES, F2, F1, 0);

    int dup = (out_size >= 2 * N_NODES * F2) ? 1 : 0;
    attn2_lsm_kernel<<<(N_NODES + 3) / 4, 128>>>(q2, k2, v2, r2, wb2,
                                                 (float*)d_out, dup);

    cudaEventDestroy(evFork);
    cudaEventDestroy(evCsr);
    cudaStreamDestroy(s2);
}